// round 15
// baseline (speedup 1.0000x reference)
#include <cuda_runtime.h>
#include <cstdint>

// Problem constants (fixed by reference setup_inputs)
#define NB    8        // batch
#define NS    4096     // source points
#define NT    16384    // target points
#define NC    8        // channels
#define NH    10       // neighbors
#define WPB   8        // warps per block
#define FULLM 0xFFFFFFFFu

typedef unsigned long long ull;

#define BUFCAP 288     // per-warp candidate buffer (worst case 22 + 256)
#define TRIG   23      // drain when count >= TRIG

// Bitonic sort of 32 u64 keys across a warp (ascending; lane k ends with k-th smallest).
__device__ __forceinline__ ull bitonic32(ull key, int lane) {
#pragma unroll
    for (int k = 2; k <= 32; k <<= 1) {
#pragma unroll
        for (int j = k >> 1; j > 0; j >>= 1) {
            ull other = __shfl_xor_sync(FULLM, key, j);
            bool up    = ((lane & k) == 0);
            bool lower = ((lane & j) == 0);
            ull mn = (key < other) ? key : other;
            ull mx = (key < other) ? other : key;
            key = (lower == up) ? mn : mx;
        }
    }
    return key;
}

// Merge buffered candidates into the distributed top-10 (lanes 0..9), refresh thr.
// count is a uniform register; scnt (shared) is only the atomic offset allocator.
__device__ __noinline__ void drain(ull& top, ull* __restrict__ buf,
                                   int* __restrict__ scnt, int& count,
                                   int lane, float& thr) {
    __syncwarp(FULLM);           // order STS/ATOMS pushes before LDS reads
    int cur = 0;
    while (cur < count) {
        int take = count - cur;
        if (take > 22) take = 22;
        ull v;
        if (lane < NH) {
            v = top;
        } else {
            int b = lane - NH;
            v = (b < take) ? buf[cur + b] : ~0ULL;
        }
        v = bitonic32(v, lane);
        if (lane < NH) top = v;
        cur += take;
    }
    count = 0;
    if (lane == 0) *scnt = 0;
    thr = __uint_as_float((unsigned)(__shfl_sync(FULLM, top, NH - 1) >> 32));
    __syncwarp(FULLM);           // buf reads + reset done before next batch pushes
}

#define MKKEY(dv, sidx) ((((ull)__float_as_uint(dv)) << 32) | (unsigned)(sidx))

// Distances for one 4-float4 batch.
#define DIST8(P0, P1, P2, P3)                                                 \
    float d0 = P0.x * P0.x + P0.y * P0.y;                                     \
    float d1 = P0.z * P0.z + P0.w * P0.w;                                     \
    float d2 = P1.x * P1.x + P1.y * P1.y;                                     \
    float d3 = P1.z * P1.z + P1.w * P1.w;                                     \
    float d4 = P2.x * P2.x + P2.y * P2.y;                                     \
    float d5 = P2.z * P2.z + P2.w * P2.w;                                     \
    float d6 = P3.x * P3.x + P3.y * P3.y;                                     \
    float d7 = P3.z * P3.z + P3.w * P3.w;

// Streaming loads (evict-first): rel is read exactly once — keep it out of L2's
// working set so the hot x-gather stays resident and LTS churn drops.
#define LOAD4(P0, P1, P2, P3, J)                                              \
    P0 = __ldcs(&relrow[(J)]);                                                \
    P1 = __ldcs(&relrow[(J) + 32]);                                           \
    P2 = __ldcs(&relrow[(J) + 64]);                                           \
    P3 = __ldcs(&relrow[(J) + 96]);

// Selection for one batch: warp-coherent prefilter, atomic-offset push,
// register count via REDUX (no per-batch __syncwarp / LDS), drain on TRIG.
#define PROCESS(JB)                                                           \
    {                                                                         \
        float mn = fminf(fminf(fminf(d0, d1), fminf(d2, d3)),                 \
                         fminf(fminf(d4, d5), fminf(d6, d7)));                \
        if (__any_sync(FULLM, mn <= thr)) {                                   \
            int c0 = d0 <= thr, c1 = d1 <= thr, c2 = d2 <= thr, c3 = d3 <= thr; \
            int c4 = d4 <= thr, c5 = d5 <= thr, c6 = d6 <= thr, c7 = d7 <= thr; \
            int cnt = c0 + c1 + c2 + c3 + c4 + c5 + c6 + c7;                  \
            int off = 0;                                                      \
            if (cnt) off = atomicAdd(scnt, cnt);                              \
            if (c0) buf[off++] = MKKEY(d0, 2 * (JB));                         \
            if (c1) buf[off++] = MKKEY(d1, 2 * (JB) + 1);                     \
            if (c2) buf[off++] = MKKEY(d2, 2 * ((JB) + 32));                  \
            if (c3) buf[off++] = MKKEY(d3, 2 * ((JB) + 32) + 1);              \
            if (c4) buf[off++] = MKKEY(d4, 2 * ((JB) + 64));                  \
            if (c5) buf[off++] = MKKEY(d5, 2 * ((JB) + 64) + 1);              \
            if (c6) buf[off++] = MKKEY(d6, 2 * ((JB) + 96));                  \
            if (c7) buf[off++] = MKKEY(d7, 2 * ((JB) + 96) + 1);              \
            count += __reduce_add_sync(FULLM, cnt);   /* uniform */           \
            if (count >= TRIG) drain(top, buf, scnt, count, lane, thr);       \
        }                                                                     \
    }

__global__ __launch_bounds__(32 * WPB, 5)
void knn_idw_kernel(const float* __restrict__ x,    // [NB, NS, NC]
                    const float* __restrict__ rel,  // [NT, NS, 2]
                    float* __restrict__ out)        // [NB, NT, NC]
{
    __shared__ ull sbuf[WPB][BUFCAP];
    __shared__ int scount[WPB];

    const int warp = threadIdx.x >> 5;
    const int lane = threadIdx.x & 31;
    const int t    = blockIdx.x * WPB + warp;     // target index (grid covers NT)
    ull* buf  = sbuf[warp];
    int* scnt = &scount[warp];

    if (lane == 0) *scnt = 0;                     // per-warp init (no block sync needed)

    const float4* relrow = reinterpret_cast<const float4*>(rel + (size_t)t * NS * 2);

    // Distributed warp top-10: lane k (k<10) holds k-th smallest key.
    // key = (float_bits(d2) << 32) | source_index -> exact order, ties by lowest idx.
    ull   top   = ~0ULL;
    float thr;
    int   count = 0;                              // uniform register copy of buffer count

    // ---- Prefetch distance 1 (4 LDG.128 in flight; MLP comes from 40 warps/SM) ----
    float4 v0, v1, v2, v3;
    LOAD4(v0, v1, v2, v3, lane);                  // batch 0

    // ---- Batch 0 (peeled): seed thr, push survivors, then FORCE a drain so thr
    //      becomes the true 10th-smallest of the first 256 elements.
    {
        const int jb = lane;
        DIST8(v0, v1, v2, v3);
        LOAD4(v0, v1, v2, v3, lane + 128);        // prefetch batch 1
        float mn = fminf(fminf(fminf(d0, d1), fminf(d2, d3)),
                         fminf(fminf(d4, d5), fminf(d6, d7)));
        // Seed thr: 10th-smallest of 32 lane-mins >= global 10th of batch 0:
        // conservative, so no true top-10 member is ever rejected.
        ull sorted = bitonic32(MKKEY(mn, lane), lane);
        thr = __uint_as_float((unsigned)(__shfl_sync(FULLM, sorted, NH - 1) >> 32));
        PROCESS(jb);
        if (count > 0) drain(top, buf, scnt, count, lane, thr);  // thr = exact 10th of 256
    }

    // ---- Steady state: batches 1..15 (unroll 2: interleave two batches' chains) ----
#pragma unroll 2
    for (int b = 1; b < 16; ++b) {
        const int jb = b * 128 + lane;
        DIST8(v0, v1, v2, v3);
        if (b < 15) { LOAD4(v0, v1, v2, v3, jb + 128); }   // prefetch next batch
        PROCESS(jb);
    }

    if (count > 0) drain(top, buf, scnt, count, lane, thr);

    // ---- Weights ----
    float wk[NH];
    int   ik[NH];
    float wsum = 0.0f;
#pragma unroll
    for (int k = 0; k < NH; ++k) {
        ull kk = __shfl_sync(FULLM, top, k);
        float dd = __uint_as_float((unsigned)(kk >> 32));
        ik[k] = (int)(kk & 0xFFFFFFFFu);
        float w = 1.0f / (sqrtf(dd) + 1e-10f);
        wk[k] = w;
        wsum += w;
    }
    const float inv = 1.0f / wsum;

    // ---- Gather + weighted sum: 64 outputs (8 batch x 8 chan), 2 per lane ----
    const int bb = lane >> 3;      // 0..3
    const int c  = lane & 7;       // 0..7
    float acc0 = 0.0f, acc1 = 0.0f;
#pragma unroll
    for (int k = 0; k < NH; ++k) {
        float w = wk[k] * inv;
        const float* xs = x + (size_t)ik[k] * NC + c;
        acc0 += w * __ldg(xs + (size_t)(bb)     * NS * NC);
        acc1 += w * __ldg(xs + (size_t)(bb + 4) * NS * NC);
    }
    out[((size_t)(bb)     * NT + t) * NC + c] = acc0;
    out[((size_t)(bb + 4) * NT + t) * NC + c] = acc1;
}

extern "C" void kernel_launch(void* const* d_in, const int* in_sizes, int n_in,
                              void* d_out, int out_size)
{
    const float* x   = (const float*)d_in[0];   // [8, 4096, 8]
    const float* rel = (const float*)d_in[1];   // [16384, 4096, 2]
    float* out       = (float*)d_out;           // [8, 16384, 8]
    (void)in_sizes; (void)n_in; (void)out_size;

    dim3 grid(NT / WPB);      // 2048 blocks
    dim3 block(32 * WPB);     // 256 threads
    knn_idw_kernel<<<grid, block>>>(x, rel, out);
}

// round 16
// speedup vs baseline: 1.0052x; 1.0052x over previous
#include <cuda_runtime.h>
#include <cstdint>

// Problem constants (fixed by reference setup_inputs)
#define NB    8        // batch
#define NS    4096     // source points
#define NT    16384    // target points
#define NC    8        // channels
#define NH    10       // neighbors
#define WPB   8        // warps per block
#define FULLM 0xFFFFFFFFu

typedef unsigned long long ull;

#define BUFCAP 288     // per-warp candidate buffer (worst case 22 + 256)
#define TRIG   23      // drain when count >= TRIG

// Bitonic sort of 32 u64 keys across a warp (ascending; lane k ends with k-th smallest).
__device__ __forceinline__ ull bitonic32(ull key, int lane) {
#pragma unroll
    for (int k = 2; k <= 32; k <<= 1) {
#pragma unroll
        for (int j = k >> 1; j > 0; j >>= 1) {
            ull other = __shfl_xor_sync(FULLM, key, j);
            bool up    = ((lane & k) == 0);
            bool lower = ((lane & j) == 0);
            ull mn = (key < other) ? key : other;
            ull mx = (key < other) ? other : key;
            key = (lower == up) ? mn : mx;
        }
    }
    return key;
}

// Merge buffered candidates into the distributed top-10 (lanes 0..9), refresh thr.
// count is a uniform register; scnt (shared) is only the atomic offset allocator.
__device__ __noinline__ void drain(ull& top, ull* __restrict__ buf,
                                   int* __restrict__ scnt, int& count,
                                   int lane, float& thr) {
    __syncwarp(FULLM);           // order STS/ATOMS pushes before LDS reads
    int cur = 0;
    while (cur < count) {
        int take = count - cur;
        if (take > 22) take = 22;
        ull v;
        if (lane < NH) {
            v = top;
        } else {
            int b = lane - NH;
            v = (b < take) ? buf[cur + b] : ~0ULL;
        }
        v = bitonic32(v, lane);
        if (lane < NH) top = v;
        cur += take;
    }
    count = 0;
    if (lane == 0) *scnt = 0;
    thr = __uint_as_float((unsigned)(__shfl_sync(FULLM, top, NH - 1) >> 32));
    __syncwarp(FULLM);           // buf reads + reset done before next batch pushes
}

#define MKKEY(dv, sidx) ((((ull)__float_as_uint(dv)) << 32) | (unsigned)(sidx))

// Distances for one 4-float4 batch.
#define DIST8(P0, P1, P2, P3)                                                 \
    float d0 = P0.x * P0.x + P0.y * P0.y;                                     \
    float d1 = P0.z * P0.z + P0.w * P0.w;                                     \
    float d2 = P1.x * P1.x + P1.y * P1.y;                                     \
    float d3 = P1.z * P1.z + P1.w * P1.w;                                     \
    float d4 = P2.x * P2.x + P2.y * P2.y;                                     \
    float d5 = P2.z * P2.z + P2.w * P2.w;                                     \
    float d6 = P3.x * P3.x + P3.y * P3.y;                                     \
    float d7 = P3.z * P3.z + P3.w * P3.w;

// Streaming loads (evict-first): rel is read exactly once — keep it out of L2's
// working set so the hot x-gather stays resident and LTS churn drops.
#define LOAD4(P0, P1, P2, P3, J)                                              \
    P0 = __ldcs(&relrow[(J)]);                                                \
    P1 = __ldcs(&relrow[(J) + 32]);                                           \
    P2 = __ldcs(&relrow[(J) + 64]);                                           \
    P3 = __ldcs(&relrow[(J) + 96]);

// Selection for one batch: warp-coherent prefilter, atomic-offset push,
// uniform register count via REDUX (no per-batch __syncwarp / LDS broadcast).
#define PROCESS(JB)                                                           \
    {                                                                         \
        float mn = fminf(fminf(fminf(d0, d1), fminf(d2, d3)),                 \
                         fminf(fminf(d4, d5), fminf(d6, d7)));                \
        if (__any_sync(FULLM, mn <= thr)) {                                   \
            int c0 = d0 <= thr, c1 = d1 <= thr, c2 = d2 <= thr, c3 = d3 <= thr; \
            int c4 = d4 <= thr, c5 = d5 <= thr, c6 = d6 <= thr, c7 = d7 <= thr; \
            int cnt = c0 + c1 + c2 + c3 + c4 + c5 + c6 + c7;                  \
            int off = 0;                                                      \
            if (cnt) off = atomicAdd(scnt, cnt);                              \
            if (c0) buf[off++] = MKKEY(d0, 2 * (JB));                         \
            if (c1) buf[off++] = MKKEY(d1, 2 * (JB) + 1);                     \
            if (c2) buf[off++] = MKKEY(d2, 2 * ((JB) + 32));                  \
            if (c3) buf[off++] = MKKEY(d3, 2 * ((JB) + 32) + 1);              \
            if (c4) buf[off++] = MKKEY(d4, 2 * ((JB) + 64));                  \
            if (c5) buf[off++] = MKKEY(d5, 2 * ((JB) + 64) + 1);              \
            if (c6) buf[off++] = MKKEY(d6, 2 * ((JB) + 96));                  \
            if (c7) buf[off++] = MKKEY(d7, 2 * ((JB) + 96) + 1);              \
            count += __reduce_add_sync(FULLM, cnt);   /* uniform */           \
            if (count >= TRIG) drain(top, buf, scnt, count, lane, thr);       \
        }                                                                     \
    }

__global__ __launch_bounds__(32 * WPB, 5)
void knn_idw_kernel(const float* __restrict__ x,    // [NB, NS, NC]
                    const float* __restrict__ rel,  // [NT, NS, 2]
                    float* __restrict__ out)        // [NB, NT, NC]
{
    __shared__ ull sbuf[WPB][BUFCAP];
    __shared__ int scount[WPB];

    const int warp = threadIdx.x >> 5;
    const int lane = threadIdx.x & 31;
    const int t    = blockIdx.x * WPB + warp;     // target index (grid covers NT)
    ull* buf  = sbuf[warp];
    int* scnt = &scount[warp];

    if (lane == 0) *scnt = 0;                     // per-warp init (no block sync needed)

    const float4* relrow = reinterpret_cast<const float4*>(rel + (size_t)t * NS * 2);

    // Distributed warp top-10: lane k (k<10) holds k-th smallest key.
    // key = (float_bits(d2) << 32) | source_index -> exact order, ties by lowest idx.
    ull   top   = ~0ULL;
    float thr;
    int   count = 0;                              // uniform register copy of buffer count

    // ---- Prefetch distance 1 (4 LDG.128 in flight; MLP comes from 40 warps/SM) ----
    float4 v0, v1, v2, v3;
    LOAD4(v0, v1, v2, v3, lane);                  // batch 0

    // ---- Batch 0 (peeled): seed thr, push survivors, then FORCE a drain so thr
    //      becomes the true 10th-smallest of the first 256 elements.
    {
        const int jb = lane;
        DIST8(v0, v1, v2, v3);
        LOAD4(v0, v1, v2, v3, lane + 128);        // prefetch batch 1
        float mn = fminf(fminf(fminf(d0, d1), fminf(d2, d3)),
                         fminf(fminf(d4, d5), fminf(d6, d7)));
        // Seed thr: 10th-smallest of 32 lane-mins >= global 10th of batch 0:
        // conservative, so no true top-10 member is ever rejected.
        ull sorted = bitonic32(MKKEY(mn, lane), lane);
        thr = __uint_as_float((unsigned)(__shfl_sync(FULLM, sorted, NH - 1) >> 32));
        PROCESS(jb);
        if (count > 0) drain(top, buf, scnt, count, lane, thr);  // thr = exact 10th of 256
    }

    // ---- Steady state: batches 1..15 ----
#pragma unroll 1
    for (int b = 1; b < 16; ++b) {
        const int jb = b * 128 + lane;
        DIST8(v0, v1, v2, v3);
        if (b < 15) { LOAD4(v0, v1, v2, v3, jb + 128); }   // prefetch next batch
        PROCESS(jb);
    }

    if (count > 0) drain(top, buf, scnt, count, lane, thr);

    // ---- Weights ----
    float wk[NH];
    int   ik[NH];
    float wsum = 0.0f;
#pragma unroll
    for (int k = 0; k < NH; ++k) {
        ull kk = __shfl_sync(FULLM, top, k);
        float dd = __uint_as_float((unsigned)(kk >> 32));
        ik[k] = (int)(kk & 0xFFFFFFFFu);
        float w = 1.0f / (sqrtf(dd) + 1e-10f);
        wk[k] = w;
        wsum += w;
    }
    const float inv = 1.0f / wsum;

    // ---- Gather + weighted sum: 64 outputs (8 batch x 8 chan), 2 per lane ----
    const int bb = lane >> 3;      // 0..3
    const int c  = lane & 7;       // 0..7
    float acc0 = 0.0f, acc1 = 0.0f;
#pragma unroll
    for (int k = 0; k < NH; ++k) {
        float w = wk[k] * inv;
        const float* xs = x + (size_t)ik[k] * NC + c;
        acc0 += w * __ldg(xs + (size_t)(bb)     * NS * NC);
        acc1 += w * __ldg(xs + (size_t)(bb + 4) * NS * NC);
    }
    out[((size_t)(bb)     * NT + t) * NC + c] = acc0;
    out[((size_t)(bb + 4) * NT + t) * NC + c] = acc1;
}

extern "C" void kernel_launch(void* const* d_in, const int* in_sizes, int n_in,
                              void* d_out, int out_size)
{
    const float* x   = (const float*)d_in[0];   // [8, 4096, 8]
    const float* rel = (const float*)d_in[1];   // [16384, 4096, 2]
    float* out       = (float*)d_out;           // [8, 16384, 8]
    (void)in_sizes; (void)n_in; (void)out_size;

    dim3 grid(NT / WPB);      // 2048 blocks
    dim3 block(32 * WPB);     // 256 threads
    knn_idw_kernel<<<grid, block>>>(x, rel, out);
}

// round 17
// speedup vs baseline: 1.0711x; 1.0655x over previous
#include <cuda_runtime.h>
#include <cstdint>

// Problem constants (fixed by reference setup_inputs)
#define NB    8        // batch
#define NS    4096     // source points
#define NT    16384    // target points
#define NC    8        // channels
#define NH    10       // neighbors
#define WPB   8        // warps per block
#define FULLM 0xFFFFFFFFu

typedef unsigned long long ull;

#define BUFCAP 288     // per-warp candidate buffer (worst case 22 + 256)
#define TRIG   23      // drain when count >= TRIG

// Bitonic sort of 32 u64 keys across a warp (ascending; lane k ends with k-th smallest).
__device__ __forceinline__ ull bitonic32(ull key, int lane) {
#pragma unroll
    for (int k = 2; k <= 32; k <<= 1) {
#pragma unroll
        for (int j = k >> 1; j > 0; j >>= 1) {
            ull other = __shfl_xor_sync(FULLM, key, j);
            bool up    = ((lane & k) == 0);
            bool lower = ((lane & j) == 0);
            ull mn = (key < other) ? key : other;
            ull mx = (key < other) ? other : key;
            key = (lower == up) ? mn : mx;
        }
    }
    return key;
}

// Merge buffered candidates into the distributed top-10 (lanes 0..9), refresh thr.
// count lives in shared (scnt); reset to 0 here.
__device__ __noinline__ void drain(ull& top, ull* __restrict__ buf,
                                   int* __restrict__ scnt, int lane, float& thr) {
    __syncwarp(FULLM);           // order STS/ATOMS pushes before LDS reads
    int count = *scnt;           // broadcast read
    int cur = 0;
    while (cur < count) {
        int take = count - cur;
        if (take > 22) take = 22;
        ull v;
        if (lane < NH) {
            v = top;
        } else {
            int b = lane - NH;
            v = (b < take) ? buf[cur + b] : ~0ULL;
        }
        v = bitonic32(v, lane);
        if (lane < NH) top = v;
        cur += take;
    }
    if (lane == 0) *scnt = 0;
    thr = __uint_as_float((unsigned)(__shfl_sync(FULLM, top, NH - 1) >> 32));
    __syncwarp(FULLM);           // buf reads + reset done before next batch pushes
}

#define MKKEY(dv, sidx) ((((ull)__float_as_uint(dv)) << 32) | (unsigned)(sidx))

// Distances for one 4-float4 batch.
#define DIST8(P0, P1, P2, P3)                                                 \
    float d0 = P0.x * P0.x + P0.y * P0.y;                                     \
    float d1 = P0.z * P0.z + P0.w * P0.w;                                     \
    float d2 = P1.x * P1.x + P1.y * P1.y;                                     \
    float d3 = P1.z * P1.z + P1.w * P1.w;                                     \
    float d4 = P2.x * P2.x + P2.y * P2.y;                                     \
    float d5 = P2.z * P2.z + P2.w * P2.w;                                     \
    float d6 = P3.x * P3.x + P3.y * P3.y;                                     \
    float d7 = P3.z * P3.z + P3.w * P3.w;

// Streaming loads (evict-first): rel is read exactly once — keep it out of L2's
// working set so the hot x-gather stays resident and LTS churn drops.
#define LOAD4(P0, P1, P2, P3, J)                                              \
    P0 = __ldcs(&relrow[(J)]);                                                \
    P1 = __ldcs(&relrow[(J) + 32]);                                           \
    P2 = __ldcs(&relrow[(J) + 64]);                                           \
    P3 = __ldcs(&relrow[(J) + 96]);

// Selection for one batch: warp-coherent prefilter, atomic-offset push, drain.
// Offsets come from one shared atomicAdd per surviving lane (typically 1-3
// lanes) instead of a 5-step warp prefix scan. Buffer order differs from
// lane-order but drain fully sorts unique keys -> identical final result.
#define PROCESS(JB)                                                           \
    {                                                                         \
        float mn = fminf(fminf(fminf(d0, d1), fminf(d2, d3)),                 \
                         fminf(fminf(d4, d5), fminf(d6, d7)));                \
        if (__any_sync(FULLM, mn <= thr)) {                                   \
            int c0 = d0 <= thr, c1 = d1 <= thr, c2 = d2 <= thr, c3 = d3 <= thr; \
            int c4 = d4 <= thr, c5 = d5 <= thr, c6 = d6 <= thr, c7 = d7 <= thr; \
            int cnt = c0 + c1 + c2 + c3 + c4 + c5 + c6 + c7;                  \
            int off = 0;                                                      \
            if (cnt) off = atomicAdd(scnt, cnt);                              \
            if (c0) buf[off++] = MKKEY(d0, 2 * (JB));                         \
            if (c1) buf[off++] = MKKEY(d1, 2 * (JB) + 1);                     \
            if (c2) buf[off++] = MKKEY(d2, 2 * ((JB) + 32));                  \
            if (c3) buf[off++] = MKKEY(d3, 2 * ((JB) + 32) + 1);              \
            if (c4) buf[off++] = MKKEY(d4, 2 * ((JB) + 64));                  \
            if (c5) buf[off++] = MKKEY(d5, 2 * ((JB) + 64) + 1);              \
            if (c6) buf[off++] = MKKEY(d6, 2 * ((JB) + 96));                  \
            if (c7) buf[off++] = MKKEY(d7, 2 * ((JB) + 96) + 1);              \
            __syncwarp(FULLM);                                                \
            if (*scnt >= TRIG) drain(top, buf, scnt, lane, thr);              \
        }                                                                     \
    }

__global__ __launch_bounds__(32 * WPB, 5)
void knn_idw_kernel(const float* __restrict__ x,    // [NB, NS, NC]
                    const float* __restrict__ rel,  // [NT, NS, 2]
                    float* __restrict__ out)        // [NB, NT, NC]
{
    __shared__ ull sbuf[WPB][BUFCAP];
    __shared__ int scount[WPB];

    const int warp = threadIdx.x >> 5;
    const int lane = threadIdx.x & 31;
    const int t    = blockIdx.x * WPB + warp;     // target index (grid covers NT)
    ull* buf  = sbuf[warp];
    int* scnt = &scount[warp];

    if (lane == 0) *scnt = 0;                     // per-warp init (no block sync needed)

    const float4* relrow = reinterpret_cast<const float4*>(rel + (size_t)t * NS * 2);

    // Distributed warp top-10: lane k (k<10) holds k-th smallest key.
    // key = (float_bits(d2) << 32) | source_index -> exact order, ties by lowest idx.
    ull   top   = ~0ULL;
    float thr;

    // ---- Prefetch distance 1 (4 LDG.128 in flight; MLP comes from 40 warps/SM) ----
    float4 v0, v1, v2, v3;
    LOAD4(v0, v1, v2, v3, lane);                  // batch 0

    // ---- Batch 0 (peeled): seed thr, push survivors, then FORCE a drain so thr
    //      becomes the true 10th-smallest of the first 256 elements.
    {
        const int jb = lane;
        DIST8(v0, v1, v2, v3);
        LOAD4(v0, v1, v2, v3, lane + 128);        // prefetch batch 1
        float mn = fminf(fminf(fminf(d0, d1), fminf(d2, d3)),
                         fminf(fminf(d4, d5), fminf(d6, d7)));
        // Seed thr: 10th-smallest of 32 lane-mins >= global 10th of batch 0:
        // conservative, so no true top-10 member is ever rejected.
        ull sorted = bitonic32(MKKEY(mn, lane), lane);
        thr = __uint_as_float((unsigned)(__shfl_sync(FULLM, sorted, NH - 1) >> 32));
        PROCESS(jb);
        __syncwarp(FULLM);
        if (*scnt > 0) drain(top, buf, scnt, lane, thr);   // thr = exact 10th of 256
    }

    // ---- Steady state: batches 1..15 ----
#pragma unroll 1
    for (int b = 1; b < 16; ++b) {
        const int jb = b * 128 + lane;
        DIST8(v0, v1, v2, v3);
        if (b < 15) { LOAD4(v0, v1, v2, v3, jb + 128); }   // prefetch next batch
        PROCESS(jb);
    }

    __syncwarp(FULLM);
    if (*scnt > 0) drain(top, buf, scnt, lane, thr);

    // ---- Weights ----
    float wk[NH];
    int   ik[NH];
    float wsum = 0.0f;
#pragma unroll
    for (int k = 0; k < NH; ++k) {
        ull kk = __shfl_sync(FULLM, top, k);
        float dd = __uint_as_float((unsigned)(kk >> 32));
        ik[k] = (int)(kk & 0xFFFFFFFFu);
        float w = 1.0f / (sqrtf(dd) + 1e-10f);
        wk[k] = w;
        wsum += w;
    }
    const float inv = 1.0f / wsum;

    // ---- Gather + weighted sum: 64 outputs (8 batch x 8 chan), 2 per lane ----
    const int bb = lane >> 3;      // 0..3
    const int c  = lane & 7;       // 0..7
    float acc0 = 0.0f, acc1 = 0.0f;
#pragma unroll
    for (int k = 0; k < NH; ++k) {
        float w = wk[k] * inv;
        const float* xs = x + (size_t)ik[k] * NC + c;
        acc0 += w * __ldg(xs + (size_t)(bb)     * NS * NC);
        acc1 += w * __ldg(xs + (size_t)(bb + 4) * NS * NC);
    }
    out[((size_t)(bb)     * NT + t) * NC + c] = acc0;
    out[((size_t)(bb + 4) * NT + t) * NC + c] = acc1;
}

extern "C" void kernel_launch(void* const* d_in, const int* in_sizes, int n_in,
                              void* d_out, int out_size)
{
    const float* x   = (const float*)d_in[0];   // [8, 4096, 8]
    const float* rel = (const float*)d_in[1];   // [16384, 4096, 2]
    float* out       = (float*)d_out;           // [8, 16384, 8]
    (void)in_sizes; (void)n_in; (void)out_size;

    dim3 grid(NT / WPB);      // 2048 blocks
    dim3 block(32 * WPB);     // 256 threads
    knn_idw_kernel<<<grid, block>>>(x, rel, out);
}